// round 8
// baseline (speedup 1.0000x reference)
#include <cuda_runtime.h>
#include <cuda_bf16.h>
#include <cstdint>
#include <cstddef>

// Problem constants
#define Bc   4
#define Sc   1024
#define Dc   1024
#define Hc   16
#define HDc  64
#define Mrows (Bc * Sc)          // 4096
#define NQKV  (3 * Dc)           // 3072
#define NBLK  8                  // 1024/128 score col-blocks

static const long OUT_ELEMS = (long)Bc * Sc * Dc;        // 4,194,304
static const long ATT_ELEMS = (long)Bc * Hc * Sc * Sc;   // 67,108,864

// Scratch (device globals — no allocations allowed)
__device__ float  g_qkv[(size_t)Mrows * NQKV];           // 50 MB
__device__ float  g_ctx[(size_t)Mrows * Dc];             // 16 MB
__device__ float  g_att[(size_t)Bc * Hc * Sc * Sc];      // 268 MB raw scores
__device__ float2 g_stats[(size_t)Bc * Hc * Sc * NBLK];  // 4 MB (max, sumexp) partials

// ---------------------------------------------------------------------------
// tf32 helpers
// ---------------------------------------------------------------------------
__device__ __forceinline__ unsigned f2tf(float f) {
    unsigned u;
    asm("cvt.rna.tf32.f32 %0, %1;" : "=r"(u) : "f"(f));
    return u;
}

// D += A(16x8, row) * B(8x8, col) ; fp32 accum
__device__ __forceinline__ void mma8(float* d, const unsigned* a, const unsigned* b) {
    asm volatile(
        "mma.sync.aligned.m16n8k8.row.col.f32.tf32.tf32.f32 "
        "{%0,%1,%2,%3}, {%4,%5,%6,%7}, {%8,%9}, {%0,%1,%2,%3};\n"
        : "+f"(d[0]), "+f"(d[1]), "+f"(d[2]), "+f"(d[3])
        : "r"(a[0]), "r"(a[1]), "r"(a[2]), "r"(a[3]), "r"(b[0]), "r"(b[1]));
}

// ---------------------------------------------------------------------------
// tf32 SGEMM + bias: C[M,N] = A[M,K] @ B[K,N] + bias[N]
// 128x128 block tile, BK=16, double-buffered smem, 256 thr.
// ---------------------------------------------------------------------------
__global__ __launch_bounds__(256) void sgemm_tf32_bias(
    const float* __restrict__ A, const float* __restrict__ B,
    const float* __restrict__ bias, float* __restrict__ C,
    int Md, int Nd, int Kd)
{
    __shared__ unsigned As[2][16][132];   // [stage][k][m]
    __shared__ unsigned Bs[2][16][132];   // [stage][k][n]

    const int t    = threadIdx.x;
    const int m0   = blockIdx.y * 128;
    const int n0   = blockIdx.x * 128;
    const int warp = t >> 5, lane = t & 31;
    const int wm   = (warp & 1) * 64;
    const int wn   = (warp >> 1) * 32;
    const int q    = lane >> 2, r = lane & 3;

    float acc[4][4][4];
#pragma unroll
    for (int mt = 0; mt < 4; ++mt)
#pragma unroll
        for (int nt = 0; nt < 4; ++nt)
#pragma unroll
            for (int i = 0; i < 4; ++i) acc[mt][nt][i] = 0.0f;

#pragma unroll
    for (int i = 0; i < 2; ++i) {
        const int idx = t + i * 256;
        const int ak4 = idx >> 7, am = idx & 127;
        float4 av = *(const float4*)&A[(size_t)(m0 + am) * Kd + ak4 * 4];
        As[0][ak4 * 4 + 0][am] = f2tf(av.x);
        As[0][ak4 * 4 + 1][am] = f2tf(av.y);
        As[0][ak4 * 4 + 2][am] = f2tf(av.z);
        As[0][ak4 * 4 + 3][am] = f2tf(av.w);
        const int bk = idx >> 5, bn4 = (idx & 31) * 4;
        float4 bv = *(const float4*)&B[(size_t)bk * Nd + n0 + bn4];
        Bs[0][bk][bn4 + 0] = f2tf(bv.x);
        Bs[0][bk][bn4 + 1] = f2tf(bv.y);
        Bs[0][bk][bn4 + 2] = f2tf(bv.z);
        Bs[0][bk][bn4 + 3] = f2tf(bv.w);
    }
    __syncthreads();

    const int nK = Kd >> 4;
    for (int kt = 0; kt < nK; ++kt) {
        const int cur = kt & 1;
        float4 pa[2], pb[2];
        const bool pre = (kt + 1 < nK);
        if (pre) {
            const int kofs = (kt + 1) * 16;
#pragma unroll
            for (int i = 0; i < 2; ++i) {
                const int idx = t + i * 256;
                const int ak4 = idx >> 7, am = idx & 127;
                pa[i] = *(const float4*)&A[(size_t)(m0 + am) * Kd + kofs + ak4 * 4];
                const int bk = idx >> 5, bn4 = (idx & 31) * 4;
                pb[i] = *(const float4*)&B[(size_t)(kofs + bk) * Nd + n0 + bn4];
            }
        }

#pragma unroll
        for (int ks = 0; ks < 16; ks += 8) {
            unsigned af[4][4], bf[4][2];
#pragma unroll
            for (int mt = 0; mt < 4; ++mt) {
                const int mm = wm + mt * 16;
                af[mt][0] = As[cur][ks + r][mm + q];
                af[mt][1] = As[cur][ks + r][mm + q + 8];
                af[mt][2] = As[cur][ks + r + 4][mm + q];
                af[mt][3] = As[cur][ks + r + 4][mm + q + 8];
            }
#pragma unroll
            for (int nt = 0; nt < 4; ++nt) {
                const int nn = wn + nt * 8;
                bf[nt][0] = Bs[cur][ks + r][nn + q];
                bf[nt][1] = Bs[cur][ks + r + 4][nn + q];
            }
#pragma unroll
            for (int mt = 0; mt < 4; ++mt)
#pragma unroll
                for (int nt = 0; nt < 4; ++nt)
                    mma8(acc[mt][nt], af[mt], bf[nt]);
        }

        if (pre) {
            const int nxt = cur ^ 1;
#pragma unroll
            for (int i = 0; i < 2; ++i) {
                const int idx = t + i * 256;
                const int ak4 = idx >> 7, am = idx & 127;
                As[nxt][ak4 * 4 + 0][am] = f2tf(pa[i].x);
                As[nxt][ak4 * 4 + 1][am] = f2tf(pa[i].y);
                As[nxt][ak4 * 4 + 2][am] = f2tf(pa[i].z);
                As[nxt][ak4 * 4 + 3][am] = f2tf(pa[i].w);
                const int bk = idx >> 5, bn4 = (idx & 31) * 4;
                Bs[nxt][bk][bn4 + 0] = f2tf(pb[i].x);
                Bs[nxt][bk][bn4 + 1] = f2tf(pb[i].y);
                Bs[nxt][bk][bn4 + 2] = f2tf(pb[i].z);
                Bs[nxt][bk][bn4 + 3] = f2tf(pb[i].w);
            }
        }
        __syncthreads();
    }

#pragma unroll
    for (int mt = 0; mt < 4; ++mt) {
        const int row0 = m0 + wm + mt * 16 + q;
#pragma unroll
        for (int nt = 0; nt < 4; ++nt) {
            const int col = n0 + wn + nt * 8 + 2 * r;
            const float bx = bias[col], by = bias[col + 1];
            float2 v0 = make_float2(acc[mt][nt][0] + bx, acc[mt][nt][1] + by);
            float2 v1 = make_float2(acc[mt][nt][2] + bx, acc[mt][nt][3] + by);
            *(float2*)&C[(size_t)row0 * Nd + col] = v0;
            *(float2*)&C[(size_t)(row0 + 8) * Nd + col] = v1;
        }
    }
}

// ---------------------------------------------------------------------------
// scores: raw[b,h,m,n] = (Q.K)*0.125 + mask  -> scratch
// Also emits per-row block-partial softmax stats (max over 128 cols,
// sum of exp(s - max)) into g_stats[(bh*S+m)*8 + nblk].
// ---------------------------------------------------------------------------
__global__ __launch_bounds__(256) void scores_tf32(
    const float* __restrict__ qkv, const float* __restrict__ mask,
    float* __restrict__ sraw, float2* __restrict__ stats)
{
    __shared__ unsigned Qs[2][16][132];
    __shared__ unsigned Ks[2][16][132];
    __shared__ float smax[4][128];
    __shared__ float ssum[4][128];

    const int t    = threadIdx.x;
    const int bh   = blockIdx.z;
    const int b    = bh >> 4, h = bh & 15;
    const int m0   = blockIdx.y * 128;
    const int n0   = blockIdx.x * 128;
    const int warp = t >> 5, lane = t & 31;
    const int wm   = (warp & 1) * 64;
    const int wn   = (warp >> 1) * 32;
    const int ngrp = warp >> 1;          // which 32-col group
    const int q    = lane >> 2, r = lane & 3;

    const size_t qbase = (size_t)b * Sc * NQKV + (size_t)h * 192;

    float acc[4][4][4];
#pragma unroll
    for (int mt = 0; mt < 4; ++mt)
#pragma unroll
        for (int nt = 0; nt < 4; ++nt)
#pragma unroll
            for (int i = 0; i < 4; ++i) acc[mt][nt][i] = 0.0f;

#pragma unroll
    for (int i = 0; i < 2; ++i) {
        const int idx = t + i * 256;
        const int k4 = idx >> 7, row = idx & 127;
        float4 qv = *(const float4*)&qkv[qbase + (size_t)(m0 + row) * NQKV + k4 * 4];
        float4 kv = *(const float4*)&qkv[qbase + (size_t)(n0 + row) * NQKV + 64 + k4 * 4];
        Qs[0][k4 * 4 + 0][row] = f2tf(qv.x);
        Qs[0][k4 * 4 + 1][row] = f2tf(qv.y);
        Qs[0][k4 * 4 + 2][row] = f2tf(qv.z);
        Qs[0][k4 * 4 + 3][row] = f2tf(qv.w);
        Ks[0][k4 * 4 + 0][row] = f2tf(kv.x);
        Ks[0][k4 * 4 + 1][row] = f2tf(kv.y);
        Ks[0][k4 * 4 + 2][row] = f2tf(kv.z);
        Ks[0][k4 * 4 + 3][row] = f2tf(kv.w);
    }
    __syncthreads();

    const int nK = 4;  // 64/16
#pragma unroll
    for (int kt = 0; kt < nK; ++kt) {
        const int cur = kt & 1;
        float4 pq[2], pk[2];
        const bool pre = (kt + 1 < nK);
        if (pre) {
            const int kofs = (kt + 1) * 16;
#pragma unroll
            for (int i = 0; i < 2; ++i) {
                const int idx = t + i * 256;
                const int k4 = idx >> 7, row = idx & 127;
                pq[i] = *(const float4*)&qkv[qbase + (size_t)(m0 + row) * NQKV + kofs + k4 * 4];
                pk[i] = *(const float4*)&qkv[qbase + (size_t)(n0 + row) * NQKV + 64 + kofs + k4 * 4];
            }
        }

#pragma unroll
        for (int ks = 0; ks < 16; ks += 8) {
            unsigned af[4][4], bf[4][2];
#pragma unroll
            for (int mt = 0; mt < 4; ++mt) {
                const int mm = wm + mt * 16;
                af[mt][0] = Qs[cur][ks + r][mm + q];
                af[mt][1] = Qs[cur][ks + r][mm + q + 8];
                af[mt][2] = Qs[cur][ks + r + 4][mm + q];
                af[mt][3] = Qs[cur][ks + r + 4][mm + q + 8];
            }
#pragma unroll
            for (int nt = 0; nt < 4; ++nt) {
                const int nn = wn + nt * 8;
                bf[nt][0] = Ks[cur][ks + r][nn + q];
                bf[nt][1] = Ks[cur][ks + r + 4][nn + q];
            }
#pragma unroll
            for (int mt = 0; mt < 4; ++mt)
#pragma unroll
                for (int nt = 0; nt < 4; ++nt)
                    mma8(acc[mt][nt], af[mt], bf[nt]);
        }

        if (pre) {
            const int nxt = cur ^ 1;
#pragma unroll
            for (int i = 0; i < 2; ++i) {
                const int idx = t + i * 256;
                const int k4 = idx >> 7, row = idx & 127;
                Qs[nxt][k4 * 4 + 0][row] = f2tf(pq[i].x);
                Qs[nxt][k4 * 4 + 1][row] = f2tf(pq[i].y);
                Qs[nxt][k4 * 4 + 2][row] = f2tf(pq[i].z);
                Qs[nxt][k4 * 4 + 3][row] = f2tf(pq[i].w);
                Ks[nxt][k4 * 4 + 0][row] = f2tf(pk[i].x);
                Ks[nxt][k4 * 4 + 1][row] = f2tf(pk[i].y);
                Ks[nxt][k4 * 4 + 2][row] = f2tf(pk[i].z);
                Ks[nxt][k4 * 4 + 3][row] = f2tf(pk[i].w);
            }
        }
        __syncthreads();
    }

    const float scale = 0.125f;
    const float* mbase = mask + (size_t)b * Sc * Sc;
    float* abase = sraw + (size_t)bh * Sc * Sc;

    // epilogue: finalize raw scores in regs, write, track per-row max
    float rmax[4][2];
#pragma unroll
    for (int mt = 0; mt < 4; ++mt) { rmax[mt][0] = -1e30f; rmax[mt][1] = -1e30f; }

#pragma unroll
    for (int mt = 0; mt < 4; ++mt) {
        const int row0 = m0 + wm + mt * 16 + q;
#pragma unroll
        for (int nt = 0; nt < 4; ++nt) {
            const int col = n0 + wn + nt * 8 + 2 * r;
            float2 mv0 = *(const float2*)&mbase[(size_t)row0 * Sc + col];
            float2 mv1 = *(const float2*)&mbase[(size_t)(row0 + 8) * Sc + col];
            acc[mt][nt][0] = fmaf(acc[mt][nt][0], scale, mv0.x);
            acc[mt][nt][1] = fmaf(acc[mt][nt][1], scale, mv0.y);
            acc[mt][nt][2] = fmaf(acc[mt][nt][2], scale, mv1.x);
            acc[mt][nt][3] = fmaf(acc[mt][nt][3], scale, mv1.y);
            *(float2*)&abase[(size_t)row0 * Sc + col] =
                make_float2(acc[mt][nt][0], acc[mt][nt][1]);
            *(float2*)&abase[(size_t)(row0 + 8) * Sc + col] =
                make_float2(acc[mt][nt][2], acc[mt][nt][3]);
            rmax[mt][0] = fmaxf(rmax[mt][0], fmaxf(acc[mt][nt][0], acc[mt][nt][1]));
            rmax[mt][1] = fmaxf(rmax[mt][1], fmaxf(acc[mt][nt][2], acc[mt][nt][3]));
        }
    }
    // reduce max over r lanes (32 cols per warp)
#pragma unroll
    for (int mt = 0; mt < 4; ++mt)
#pragma unroll
        for (int i = 0; i < 2; ++i) {
            float m_ = rmax[mt][i];
            m_ = fmaxf(m_, __shfl_xor_sync(0xffffffffu, m_, 1));
            m_ = fmaxf(m_, __shfl_xor_sync(0xffffffffu, m_, 2));
            rmax[mt][i] = m_;
        }
    if (r == 0) {
#pragma unroll
        for (int mt = 0; mt < 4; ++mt) {
            smax[ngrp][wm + mt * 16 + q]     = rmax[mt][0];
            smax[ngrp][wm + mt * 16 + q + 8] = rmax[mt][1];
        }
    }
    __syncthreads();
    // exp-sum relative to 128-col block max
#pragma unroll
    for (int mt = 0; mt < 4; ++mt) {
#pragma unroll
        for (int i = 0; i < 2; ++i) {
            const int row = wm + mt * 16 + q + i * 8;
            const float M = fmaxf(fmaxf(smax[0][row], smax[1][row]),
                                  fmaxf(smax[2][row], smax[3][row]));
            float s = 0.0f;
#pragma unroll
            for (int nt = 0; nt < 4; ++nt) {
                s += __expf(acc[mt][nt][2 * i]     - M);
                s += __expf(acc[mt][nt][2 * i + 1] - M);
            }
            s += __shfl_xor_sync(0xffffffffu, s, 1);
            s += __shfl_xor_sync(0xffffffffu, s, 2);
            if (r == 0) ssum[ngrp][row] = s;
        }
    }
    __syncthreads();
    if (t < 128) {
        const int row = t;
        const float M = fmaxf(fmaxf(smax[0][row], smax[1][row]),
                              fmaxf(smax[2][row], smax[3][row]));
        const float l = ssum[0][row] + ssum[1][row] + ssum[2][row] + ssum[3][row];
        stats[((size_t)bh * Sc + m0 + row) * NBLK + blockIdx.x] = make_float2(M, l);
    }
}

// ---------------------------------------------------------------------------
// ctx: fused softmax-normalize + att-output write + att@V.
// Reads raw scores + stats; writes normalized att (optional) and ctx.
// Block 128(M)x64(N), BK=16 double-buffered. Warp grid 4(M)x2(N).
// ---------------------------------------------------------------------------
__global__ __launch_bounds__(256) void ctx_tf32(
    const float* __restrict__ sraw, const float2* __restrict__ stats,
    const float* __restrict__ qkv, float* __restrict__ attOut,
    float* __restrict__ ctx, int write_att)
{
    __shared__ unsigned As[2][16][132];   // normalized p: [k][m]
    __shared__ unsigned Vs[2][16][68];    // V: [k][n]
    __shared__ float Ms[128], Is[128];

    const int t    = threadIdx.x;
    const int bh   = blockIdx.z;
    const int b    = bh >> 4, h = bh & 15;
    const int m0   = blockIdx.y * 128;
    const int warp = t >> 5, lane = t & 31;
    const int wm   = (warp & 3) * 32;
    const int wn   = (warp >> 2) * 32;
    const int q    = lane >> 2, r = lane & 3;

    const float* abase = sraw + (size_t)bh * Sc * Sc;
    float* obase = attOut + (size_t)bh * Sc * Sc;
    const size_t vbase = (size_t)b * Sc * NQKV + (size_t)h * 192 + 128;

    // Combine per-block stats -> final (M, 1/L) per row
    if (t < 128) {
        const float2* st = &stats[((size_t)bh * Sc + m0 + t) * NBLK];
        float2 v[NBLK];
#pragma unroll
        for (int j = 0; j < NBLK; ++j) v[j] = st[j];
        float M = v[0].x;
#pragma unroll
        for (int j = 1; j < NBLK; ++j) M = fmaxf(M, v[j].x);
        float L = 0.0f;
#pragma unroll
        for (int j = 0; j < NBLK; ++j) L += v[j].y * __expf(v[j].x - M);
        Ms[t] = M;
        Is[t] = 1.0f / L;
    }
    __syncthreads();
    const float rowM = Ms[t & 127];
    const float rowI = Is[t & 127];

    float acc[2][4][4];
#pragma unroll
    for (int mt = 0; mt < 2; ++mt)
#pragma unroll
        for (int nt = 0; nt < 4; ++nt)
#pragma unroll
            for (int i = 0; i < 4; ++i) acc[mt][nt][i] = 0.0f;

    // tile 0
#pragma unroll
    for (int i = 0; i < 2; ++i) {
        const int idx = t + i * 256;
        const int k4 = idx >> 7, m = idx & 127;
        float4 av = *(const float4*)&abase[(size_t)(m0 + m) * Sc + k4 * 4];
        av.x = __expf(av.x - rowM) * rowI;
        av.y = __expf(av.y - rowM) * rowI;
        av.z = __expf(av.z - rowM) * rowI;
        av.w = __expf(av.w - rowM) * rowI;
        if (write_att) *(float4*)&obase[(size_t)(m0 + m) * Sc + k4 * 4] = av;
        As[0][k4 * 4 + 0][m] = f2tf(av.x);
        As[0][k4 * 4 + 1][m] = f2tf(av.y);
        As[0][k4 * 4 + 2][m] = f2tf(av.z);
        As[0][k4 * 4 + 3][m] = f2tf(av.w);
    }
    {
        const int vk = t >> 4, vn4 = (t & 15) * 4;
        float4 vv = *(const float4*)&qkv[vbase + (size_t)vk * NQKV + vn4];
        Vs[0][vk][vn4 + 0] = f2tf(vv.x);
        Vs[0][vk][vn4 + 1] = f2tf(vv.y);
        Vs[0][vk][vn4 + 2] = f2tf(vv.z);
        Vs[0][vk][vn4 + 3] = f2tf(vv.w);
    }
    __syncthreads();

    const int nK = Sc >> 4;   // 64
    for (int kt = 0; kt < nK; ++kt) {
        const int cur = kt & 1;
        float4 pa[2], pv;
        const bool pre = (kt + 1 < nK);
        const int kofs = (kt + 1) * 16;
        if (pre) {
#pragma unroll
            for (int i = 0; i < 2; ++i) {
                const int idx = t + i * 256;
                const int k4 = idx >> 7, m = idx & 127;
                pa[i] = *(const float4*)&abase[(size_t)(m0 + m) * Sc + kofs + k4 * 4];
            }
            const int vk = t >> 4, vn4 = (t & 15) * 4;
            pv = *(const float4*)&qkv[vbase + (size_t)(kofs + vk) * NQKV + vn4];
        }

#pragma unroll
        for (int ks = 0; ks < 16; ks += 8) {
            unsigned af[2][4], bf[4][2];
#pragma unroll
            for (int mt = 0; mt < 2; ++mt) {
                const int mm = wm + mt * 16;
                af[mt][0] = As[cur][ks + r][mm + q];
                af[mt][1] = As[cur][ks + r][mm + q + 8];
                af[mt][2] = As[cur][ks + r + 4][mm + q];
                af[mt][3] = As[cur][ks + r + 4][mm + q + 8];
            }
#pragma unroll
            for (int nt = 0; nt < 4; ++nt) {
                const int nn = wn + nt * 8;
                bf[nt][0] = Vs[cur][ks + r][nn + q];
                bf[nt][1] = Vs[cur][ks + r + 4][nn + q];
            }
#pragma unroll
            for (int mt = 0; mt < 2; ++mt)
#pragma unroll
                for (int nt = 0; nt < 4; ++nt)
                    mma8(acc[mt][nt], af[mt], bf[nt]);
        }

        if (pre) {
            const int nxt = cur ^ 1;
#pragma unroll
            for (int i = 0; i < 2; ++i) {
                const int idx = t + i * 256;
                const int k4 = idx >> 7, m = idx & 127;
                pa[i].x = __expf(pa[i].x - rowM) * rowI;
                pa[i].y = __expf(pa[i].y - rowM) * rowI;
                pa[i].z = __expf(pa[i].z - rowM) * rowI;
                pa[i].w = __expf(pa[i].w - rowM) * rowI;
                if (write_att)
                    *(float4*)&obase[(size_t)(m0 + m) * Sc + kofs + k4 * 4] = pa[i];
                As[nxt][k4 * 4 + 0][m] = f2tf(pa[i].x);
                As[nxt][k4 * 4 + 1][m] = f2tf(pa[i].y);
                As[nxt][k4 * 4 + 2][m] = f2tf(pa[i].z);
                As[nxt][k4 * 4 + 3][m] = f2tf(pa[i].w);
            }
            const int vk = t >> 4, vn4 = (t & 15) * 4;
            Vs[nxt][vk][vn4 + 0] = f2tf(pv.x);
            Vs[nxt][vk][vn4 + 1] = f2tf(pv.y);
            Vs[nxt][vk][vn4 + 2] = f2tf(pv.z);
            Vs[nxt][vk][vn4 + 3] = f2tf(pv.w);
        }
        __syncthreads();
    }

    // Epilogue: ctx[b, m, h, :]
#pragma unroll
    for (int mt = 0; mt < 2; ++mt) {
        const int row0 = m0 + wm + mt * 16 + q;
#pragma unroll
        for (int nt = 0; nt < 4; ++nt) {
            const int col = wn + nt * 8 + 2 * r;
            float2 v0 = make_float2(acc[mt][nt][0], acc[mt][nt][1]);
            float2 v1 = make_float2(acc[mt][nt][2], acc[mt][nt][3]);
            *(float2*)&ctx[(size_t)(b * Sc + row0) * Dc + h * HDc + col] = v0;
            *(float2*)&ctx[(size_t)(b * Sc + row0 + 8) * Dc + h * HDc + col] = v1;
        }
    }
}

// ---------------------------------------------------------------------------
// Launch
// ---------------------------------------------------------------------------
extern "C" void kernel_launch(void* const* d_in, const int* in_sizes, int n_in,
                              void* d_out, int out_size)
{
    const float* x    = (const float*)d_in[0];
    const float* mask = (const float*)d_in[1];
    const float* Wqkv = (const float*)d_in[2];
    const float* bqkv = (const float*)d_in[3];
    const float* Wo   = (const float*)d_in[4];
    const float* bo   = (const float*)d_in[5];

    float *qkvp, *ctxp, *srawp;
    float2* statsp;
    cudaGetSymbolAddress((void**)&qkvp,  g_qkv);
    cudaGetSymbolAddress((void**)&ctxp,  g_ctx);
    cudaGetSymbolAddress((void**)&srawp, g_att);
    cudaGetSymbolAddress((void**)&statsp, g_stats);

    float* outp = (float*)d_out;
    float* attp;
    int write_att = 1;
    if ((long)out_size >= OUT_ELEMS + ATT_ELEMS) {
        attp = (float*)d_out + OUT_ELEMS;          // tuple flattened: out, then att
    } else if ((long)out_size == ATT_ELEMS) {
        attp = (float*)d_out;                      // att-only output
        outp = qkvp;                               // sink (qkv dead by then)
    } else {
        attp = srawp;                              // out-only: skip att writes
        write_att = 0;
    }

    // 1. qkv = x @ Wqkv + bqkv        [4096,3072]
    {
        dim3 grid(NQKV / 128, Mrows / 128);
        sgemm_tf32_bias<<<grid, 256>>>(x, Wqkv, bqkv, qkvp, Mrows, NQKV, Dc);
    }
    // 2. raw scores (*scale + mask) + per-block softmax stats
    {
        dim3 grid(Sc / 128, Sc / 128, Bc * Hc);
        scores_tf32<<<grid, 256>>>(qkvp, mask, srawp, statsp);
    }
    // 3. fused normalize + att write + ctx = att @ V
    {
        dim3 grid(1, Sc / 128, Bc * Hc);
        ctx_tf32<<<grid, 256>>>(srawp, statsp, qkvp, attp, ctxp, write_att);
    }
    // 4. out = ctx @ Wo + bo
    {
        dim3 grid(Dc / 128, Mrows / 128);
        sgemm_tf32_bias<<<grid, 256>>>(ctxp, Wo, bo, outp, Mrows, Dc, Dc);
    }
}

// round 10
// speedup vs baseline: 1.2632x; 1.2632x over previous
#include <cuda_runtime.h>
#include <cuda_bf16.h>
#include <cstdint>
#include <cstddef>

// Problem constants
#define Bc   4
#define Sc   1024
#define Dc   1024
#define Hc   16
#define HDc  64
#define Mrows (Bc * Sc)          // 4096
#define NQKV  (3 * Dc)           // 3072
#define NBLK  8                  // 1024/128 score col-blocks

static const long OUT_ELEMS = (long)Bc * Sc * Dc;        // 4,194,304
static const long ATT_ELEMS = (long)Bc * Hc * Sc * Sc;   // 67,108,864

// Scratch (device globals — no allocations allowed)
__device__ float  g_qkv[(size_t)Mrows * NQKV];           // 50 MB
__device__ float  g_ctx[(size_t)Mrows * Dc];             // 16 MB
__device__ float  g_att[(size_t)Bc * Hc * Sc * Sc];      // 268 MB exp'd scores
__device__ float2 g_stats[(size_t)Bc * Hc * Sc * NBLK];  // 4 MB (blockmax, blocksum)

// ---------------------------------------------------------------------------
// helpers
// ---------------------------------------------------------------------------
__device__ __forceinline__ unsigned f2tf(float f) {
    unsigned u;
    asm("cvt.rna.tf32.f32 %0, %1;" : "=r"(u) : "f"(f));
    return u;
}

__device__ __forceinline__ void mma8(float* d, const unsigned* a, const unsigned* b) {
    asm volatile(
        "mma.sync.aligned.m16n8k8.row.col.f32.tf32.tf32.f32 "
        "{%0,%1,%2,%3}, {%4,%5,%6,%7}, {%8,%9}, {%0,%1,%2,%3};\n"
        : "+f"(d[0]), "+f"(d[1]), "+f"(d[2]), "+f"(d[3])
        : "r"(a[0]), "r"(a[1]), "r"(a[2]), "r"(a[3]), "r"(b[0]), "r"(b[1]));
}

__device__ __forceinline__ void cpa16(uint32_t dst, const void* src) {
    asm volatile("cp.async.cg.shared.global [%0], [%1], 16;\n" :: "r"(dst), "l"(src));
}
#define CP_COMMIT() asm volatile("cp.async.commit_group;\n" ::: "memory")
#define CP_WAIT2()  asm volatile("cp.async.wait_group 2;\n" ::: "memory")

// ---------------------------------------------------------------------------
// tf32 GEMM + bias, cp.async 4-stage pipeline, BK=8.
// C[M,N] = A[M,K] @ B[K,N] + bias[N].  128x128 block tile, 256 thr.
// A staged [m][k] (pitch 12, conflict-free), B staged [k][n] (pitch 136).
// fp32 in smem; cvt->tf32 at fragment load (rna preserved).
// ---------------------------------------------------------------------------
__global__ __launch_bounds__(256) void sgemm_tf32_bias(
    const float* __restrict__ A, const float* __restrict__ B,
    const float* __restrict__ bias, float* __restrict__ C,
    int Md, int Nd, int Kd)
{
    __shared__ __align__(16) float As[4][128][12];   // [stage][m][k] 8 used of 12
    __shared__ __align__(16) float Bs[4][8][136];    // [stage][k][n] 128 used of 136

    const int t    = threadIdx.x;
    const int m0   = blockIdx.y * 128;
    const int n0   = blockIdx.x * 128;
    const int warp = t >> 5, lane = t & 31;
    const int wm   = (warp & 1) * 64;
    const int wn   = (warp >> 1) * 32;
    const int q    = lane >> 2, r = lane & 3;

    // copy roles: A -> one 16B chunk (am, ac4); B -> one 16B chunk (bk, bn4)
    const int am  = t >> 1, ac4 = (t & 1) * 4;
    const int bk  = t >> 5, bn4 = (t & 31) * 4;
    const float* aSrcRow = &A[(size_t)(m0 + am) * Kd + ac4];
    const float* bSrcRow = &B[(size_t)bk * Nd + n0 + bn4];

    float acc[4][4][4];
#pragma unroll
    for (int mt = 0; mt < 4; ++mt)
#pragma unroll
        for (int nt = 0; nt < 4; ++nt)
#pragma unroll
            for (int i = 0; i < 4; ++i) acc[mt][nt][i] = 0.0f;

    const int nK = Kd >> 3;

    // prologue: stages 0..2
#pragma unroll
    for (int s = 0; s < 3; ++s) {
        cpa16((uint32_t)__cvta_generic_to_shared(&As[s][am][ac4]), aSrcRow + s * 8);
        cpa16((uint32_t)__cvta_generic_to_shared(&Bs[s][bk][bn4]), bSrcRow + (size_t)(s * 8) * Nd);
        CP_COMMIT();
    }

    for (int kt = 0; kt < nK; ++kt) {
        CP_WAIT2();
        __syncthreads();
        const int cur = kt & 3;

        unsigned af[4][4], bf[4][2];
#pragma unroll
        for (int mt = 0; mt < 4; ++mt) {
            const int mm = wm + mt * 16;
            af[mt][0] = f2tf(As[cur][mm + q][r]);
            af[mt][1] = f2tf(As[cur][mm + q + 8][r]);
            af[mt][2] = f2tf(As[cur][mm + q][r + 4]);
            af[mt][3] = f2tf(As[cur][mm + q + 8][r + 4]);
        }
#pragma unroll
        for (int nt = 0; nt < 4; ++nt) {
            const int nn = wn + nt * 8;
            bf[nt][0] = f2tf(Bs[cur][r][nn + q]);
            bf[nt][1] = f2tf(Bs[cur][r + 4][nn + q]);
        }
#pragma unroll
        for (int mt = 0; mt < 4; ++mt)
#pragma unroll
            for (int nt = 0; nt < 4; ++nt)
                mma8(acc[mt][nt], af[mt], bf[nt]);

        const int nx = kt + 3;
        if (nx < nK) {
            const int s = nx & 3;
            cpa16((uint32_t)__cvta_generic_to_shared(&As[s][am][ac4]), aSrcRow + nx * 8);
            cpa16((uint32_t)__cvta_generic_to_shared(&Bs[s][bk][bn4]), bSrcRow + (size_t)(nx * 8) * Nd);
        }
        CP_COMMIT();
    }

    // Epilogue
#pragma unroll
    for (int mt = 0; mt < 4; ++mt) {
        const int row0 = m0 + wm + mt * 16 + q;
#pragma unroll
        for (int nt = 0; nt < 4; ++nt) {
            const int col = n0 + wn + nt * 8 + 2 * r;
            const float bx = bias[col], by = bias[col + 1];
            float2 v0 = make_float2(acc[mt][nt][0] + bx, acc[mt][nt][1] + by);
            float2 v1 = make_float2(acc[mt][nt][2] + bx, acc[mt][nt][3] + by);
            *(float2*)&C[(size_t)row0 * Nd + col] = v0;
            *(float2*)&C[(size_t)(row0 + 8) * Nd + col] = v1;
        }
    }
}

// ---------------------------------------------------------------------------
// scores: computes s = (Q.K)*0.125 + mask, per-128-col-block max M_b,
// writes p = exp(s - M_b) to scratch, stats = (M_b, sum p).
// (the exps were computed here anyway for the block sums — now kept,
//  removing all MUFU work from the ctx kernel's staging path.)
// ---------------------------------------------------------------------------
__global__ __launch_bounds__(256) void scores_tf32(
    const float* __restrict__ qkv, const float* __restrict__ mask,
    float* __restrict__ sexp, float2* __restrict__ stats)
{
    __shared__ unsigned Qs[2][16][132];
    __shared__ unsigned Ks[2][16][132];
    __shared__ float smax[4][128];
    __shared__ float ssum[4][128];

    const int t    = threadIdx.x;
    const int bh   = blockIdx.z;
    const int b    = bh >> 4, h = bh & 15;
    const int m0   = blockIdx.y * 128;
    const int n0   = blockIdx.x * 128;
    const int warp = t >> 5, lane = t & 31;
    const int wm   = (warp & 1) * 64;
    const int wn   = (warp >> 1) * 32;
    const int ngrp = warp >> 1;
    const int q    = lane >> 2, r = lane & 3;

    const size_t qbase = (size_t)b * Sc * NQKV + (size_t)h * 192;

    float acc[4][4][4];
#pragma unroll
    for (int mt = 0; mt < 4; ++mt)
#pragma unroll
        for (int nt = 0; nt < 4; ++nt)
#pragma unroll
            for (int i = 0; i < 4; ++i) acc[mt][nt][i] = 0.0f;

#pragma unroll
    for (int i = 0; i < 2; ++i) {
        const int idx = t + i * 256;
        const int k4 = idx >> 7, row = idx & 127;
        float4 qv = *(const float4*)&qkv[qbase + (size_t)(m0 + row) * NQKV + k4 * 4];
        float4 kv = *(const float4*)&qkv[qbase + (size_t)(n0 + row) * NQKV + 64 + k4 * 4];
        Qs[0][k4 * 4 + 0][row] = f2tf(qv.x);
        Qs[0][k4 * 4 + 1][row] = f2tf(qv.y);
        Qs[0][k4 * 4 + 2][row] = f2tf(qv.z);
        Qs[0][k4 * 4 + 3][row] = f2tf(qv.w);
        Ks[0][k4 * 4 + 0][row] = f2tf(kv.x);
        Ks[0][k4 * 4 + 1][row] = f2tf(kv.y);
        Ks[0][k4 * 4 + 2][row] = f2tf(kv.z);
        Ks[0][k4 * 4 + 3][row] = f2tf(kv.w);
    }
    __syncthreads();

    const int nK = 4;  // 64/16
#pragma unroll
    for (int kt = 0; kt < nK; ++kt) {
        const int cur = kt & 1;
        float4 pq[2], pk[2];
        const bool pre = (kt + 1 < nK);
        if (pre) {
            const int kofs = (kt + 1) * 16;
#pragma unroll
            for (int i = 0; i < 2; ++i) {
                const int idx = t + i * 256;
                const int k4 = idx >> 7, row = idx & 127;
                pq[i] = *(const float4*)&qkv[qbase + (size_t)(m0 + row) * NQKV + kofs + k4 * 4];
                pk[i] = *(const float4*)&qkv[qbase + (size_t)(n0 + row) * NQKV + 64 + kofs + k4 * 4];
            }
        }

#pragma unroll
        for (int ks = 0; ks < 16; ks += 8) {
            unsigned af[4][4], bf[4][2];
#pragma unroll
            for (int mt = 0; mt < 4; ++mt) {
                const int mm = wm + mt * 16;
                af[mt][0] = Qs[cur][ks + r][mm + q];
                af[mt][1] = Qs[cur][ks + r][mm + q + 8];
                af[mt][2] = Qs[cur][ks + r + 4][mm + q];
                af[mt][3] = Qs[cur][ks + r + 4][mm + q + 8];
            }
#pragma unroll
            for (int nt = 0; nt < 4; ++nt) {
                const int nn = wn + nt * 8;
                bf[nt][0] = Ks[cur][ks + r][nn + q];
                bf[nt][1] = Ks[cur][ks + r + 4][nn + q];
            }
#pragma unroll
            for (int mt = 0; mt < 4; ++mt)
#pragma unroll
                for (int nt = 0; nt < 4; ++nt)
                    mma8(acc[mt][nt], af[mt], bf[nt]);
        }

        if (pre) {
            const int nxt = cur ^ 1;
#pragma unroll
            for (int i = 0; i < 2; ++i) {
                const int idx = t + i * 256;
                const int k4 = idx >> 7, row = idx & 127;
                Qs[nxt][k4 * 4 + 0][row] = f2tf(pq[i].x);
                Qs[nxt][k4 * 4 + 1][row] = f2tf(pq[i].y);
                Qs[nxt][k4 * 4 + 2][row] = f2tf(pq[i].z);
                Qs[nxt][k4 * 4 + 3][row] = f2tf(pq[i].w);
                Ks[nxt][k4 * 4 + 0][row] = f2tf(pk[i].x);
                Ks[nxt][k4 * 4 + 1][row] = f2tf(pk[i].y);
                Ks[nxt][k4 * 4 + 2][row] = f2tf(pk[i].z);
                Ks[nxt][k4 * 4 + 3][row] = f2tf(pk[i].w);
            }
        }
        __syncthreads();
    }

    const float scale = 0.125f;
    const float* mbase = mask + (size_t)b * Sc * Sc;
    float* abase = sexp + (size_t)bh * Sc * Sc;

    // finalize s in regs + per-32-col-group row maxes
    float rmax[4][2];
#pragma unroll
    for (int mt = 0; mt < 4; ++mt) { rmax[mt][0] = -1e30f; rmax[mt][1] = -1e30f; }

#pragma unroll
    for (int mt = 0; mt < 4; ++mt) {
        const int row0 = m0 + wm + mt * 16 + q;
#pragma unroll
        for (int nt = 0; nt < 4; ++nt) {
            const int col = n0 + wn + nt * 8 + 2 * r;
            float2 mv0 = *(const float2*)&mbase[(size_t)row0 * Sc + col];
            float2 mv1 = *(const float2*)&mbase[(size_t)(row0 + 8) * Sc + col];
            acc[mt][nt][0] = fmaf(acc[mt][nt][0], scale, mv0.x);
            acc[mt][nt][1] = fmaf(acc[mt][nt][1], scale, mv0.y);
            acc[mt][nt][2] = fmaf(acc[mt][nt][2], scale, mv1.x);
            acc[mt][nt][3] = fmaf(acc[mt][nt][3], scale, mv1.y);
            rmax[mt][0] = fmaxf(rmax[mt][0], fmaxf(acc[mt][nt][0], acc[mt][nt][1]));
            rmax[mt][1] = fmaxf(rmax[mt][1], fmaxf(acc[mt][nt][2], acc[mt][nt][3]));
        }
    }
#pragma unroll
    for (int mt = 0; mt < 4; ++mt)
#pragma unroll
        for (int i = 0; i < 2; ++i) {
            float m_ = rmax[mt][i];
            m_ = fmaxf(m_, __shfl_xor_sync(0xffffffffu, m_, 1));
            m_ = fmaxf(m_, __shfl_xor_sync(0xffffffffu, m_, 2));
            rmax[mt][i] = m_;
        }
    if (r == 0) {
#pragma unroll
        for (int mt = 0; mt < 4; ++mt) {
            smax[ngrp][wm + mt * 16 + q]     = rmax[mt][0];
            smax[ngrp][wm + mt * 16 + q + 8] = rmax[mt][1];
        }
    }
    __syncthreads();

    // p = exp(s - blockM), write, accumulate block sums
#pragma unroll
    for (int mt = 0; mt < 4; ++mt) {
        const int lr0 = wm + mt * 16 + q;
        const int lr1 = lr0 + 8;
        const float M0 = fmaxf(fmaxf(smax[0][lr0], smax[1][lr0]),
                               fmaxf(smax[2][lr0], smax[3][lr0]));
        const float M1 = fmaxf(fmaxf(smax[0][lr1], smax[1][lr1]),
                               fmaxf(smax[2][lr1], smax[3][lr1]));
        const int row0 = m0 + lr0;
        float s0 = 0.0f, s1 = 0.0f;
#pragma unroll
        for (int nt = 0; nt < 4; ++nt) {
            const int col = n0 + wn + nt * 8 + 2 * r;
            float p0x = __expf(acc[mt][nt][0] - M0);
            float p0y = __expf(acc[mt][nt][1] - M0);
            float p1x = __expf(acc[mt][nt][2] - M1);
            float p1y = __expf(acc[mt][nt][3] - M1);
            *(float2*)&abase[(size_t)row0 * Sc + col]       = make_float2(p0x, p0y);
            *(float2*)&abase[(size_t)(row0 + 8) * Sc + col] = make_float2(p1x, p1y);
            s0 += p0x + p0y;
            s1 += p1x + p1y;
        }
        s0 += __shfl_xor_sync(0xffffffffu, s0, 1);
        s0 += __shfl_xor_sync(0xffffffffu, s0, 2);
        s1 += __shfl_xor_sync(0xffffffffu, s1, 1);
        s1 += __shfl_xor_sync(0xffffffffu, s1, 2);
        if (r == 0) { ssum[ngrp][lr0] = s0; ssum[ngrp][lr1] = s1; }
    }
    __syncthreads();
    if (t < 128) {
        const int row = t;
        const float M = fmaxf(fmaxf(smax[0][row], smax[1][row]),
                              fmaxf(smax[2][row], smax[3][row]));
        const float l = ssum[0][row] + ssum[1][row] + ssum[2][row] + ssum[3][row];
        stats[((size_t)bh * Sc + m0 + row) * NBLK + blockIdx.x] = make_float2(M, l);
    }
}

// ---------------------------------------------------------------------------
// ctx: reads p = exp(s - M_b); applies per-(row, colblock) factor
// f = exp(M_b - M)/L (pure FMUL — no exps here); optional att write; att@V.
// Block 128(M)x64(N), BK=16 double-buffered. Warp grid 4(M)x2(N).
// ---------------------------------------------------------------------------
__global__ __launch_bounds__(256) void ctx_tf32(
    const float* __restrict__ sexp, const float2* __restrict__ stats,
    const float* __restrict__ qkv, float* __restrict__ attOut,
    float* __restrict__ ctx, int write_att)
{
    __shared__ unsigned As[2][16][132];   // normalized p: [k][m]
    __shared__ unsigned Vs[2][16][68];    // V: [k][n]
    __shared__ float Fs[128][9];          // per-row, per-colblock factor (pad 9)

    const int t    = threadIdx.x;
    const int bh   = blockIdx.z;
    const int b    = bh >> 4, h = bh & 15;
    const int m0   = blockIdx.y * 128;
    const int warp = t >> 5, lane = t & 31;
    const int wm   = (warp & 3) * 32;
    const int wn   = (warp >> 2) * 32;
    const int q    = lane >> 2, r = lane & 3;

    const float* abase = sexp + (size_t)bh * Sc * Sc;
    float* obase = attOut + (size_t)bh * Sc * Sc;
    const size_t vbase = (size_t)b * Sc * NQKV + (size_t)h * 192 + 128;

    // combine per-block stats -> factors
    if (t < 128) {
        const float2* st = &stats[((size_t)bh * Sc + m0 + t) * NBLK];
        float2 v[NBLK];
#pragma unroll
        for (int j = 0; j < NBLK; ++j) v[j] = st[j];
        float M = v[0].x;
#pragma unroll
        for (int j = 1; j < NBLK; ++j) M = fmaxf(M, v[j].x);
        float e[NBLK];
        float L = 0.0f;
#pragma unroll
        for (int j = 0; j < NBLK; ++j) { e[j] = __expf(v[j].x - M); L += v[j].y * e[j]; }
        const float invL = 1.0f / L;
#pragma unroll
        for (int j = 0; j < NBLK; ++j) Fs[t][j] = e[j] * invL;
    }
    __syncthreads();

    float acc[2][4][4];
#pragma unroll
    for (int mt = 0; mt < 2; ++mt)
#pragma unroll
        for (int nt = 0; nt < 4; ++nt)
#pragma unroll
            for (int i = 0; i < 4; ++i) acc[mt][nt][i] = 0.0f;

    // tile 0 (colblock 0)
#pragma unroll
    for (int i = 0; i < 2; ++i) {
        const int idx = t + i * 256;
        const int k4 = idx >> 7, m = idx & 127;
        float4 av = *(const float4*)&abase[(size_t)(m0 + m) * Sc + k4 * 4];
        const float f = Fs[m][0];
        av.x *= f; av.y *= f; av.z *= f; av.w *= f;
        if (write_att) *(float4*)&obase[(size_t)(m0 + m) * Sc + k4 * 4] = av;
        As[0][k4 * 4 + 0][m] = f2tf(av.x);
        As[0][k4 * 4 + 1][m] = f2tf(av.y);
        As[0][k4 * 4 + 2][m] = f2tf(av.z);
        As[0][k4 * 4 + 3][m] = f2tf(av.w);
    }
    {
        const int vk = t >> 4, vn4 = (t & 15) * 4;
        float4 vv = *(const float4*)&qkv[vbase + (size_t)vk * NQKV + vn4];
        Vs[0][vk][vn4 + 0] = f2tf(vv.x);
        Vs[0][vk][vn4 + 1] = f2tf(vv.y);
        Vs[0][vk][vn4 + 2] = f2tf(vv.z);
        Vs[0][vk][vn4 + 3] = f2tf(vv.w);
    }
    __syncthreads();

    const int nK = Sc >> 4;   // 64
    for (int kt = 0; kt < nK; ++kt) {
        const int cur = kt & 1;
        float4 pa[2], pv;
        const bool pre = (kt + 1 < nK);
        const int kofs = (kt + 1) * 16;
        if (pre) {
#pragma unroll
            for (int i = 0; i < 2; ++i) {
                const int idx = t + i * 256;
                const int k4 = idx >> 7, m = idx & 127;
                pa[i] = *(const float4*)&abase[(size_t)(m0 + m) * Sc + kofs + k4 * 4];
            }
            const int vk = t >> 4, vn4 = (t & 15) * 4;
            pv = *(const float4*)&qkv[vbase + (size_t)(kofs + vk) * NQKV + vn4];
        }

#pragma unroll
        for (int ks = 0; ks < 16; ks += 8) {
            unsigned af[2][4], bf[4][2];
#pragma unroll
            for (int mt = 0; mt < 2; ++mt) {
                const int mm = wm + mt * 16;
                af[mt][0] = As[cur][ks + r][mm + q];
                af[mt][1] = As[cur][ks + r][mm + q + 8];
                af[mt][2] = As[cur][ks + r + 4][mm + q];
                af[mt][3] = As[cur][ks + r + 4][mm + q + 8];
            }
#pragma unroll
            for (int nt = 0; nt < 4; ++nt) {
                const int nn = wn + nt * 8;
                bf[nt][0] = Vs[cur][ks + r][nn + q];
                bf[nt][1] = Vs[cur][ks + r + 4][nn + q];
            }
#pragma unroll
            for (int mt = 0; mt < 2; ++mt)
#pragma unroll
                for (int nt = 0; nt < 4; ++nt)
                    mma8(acc[mt][nt], af[mt], bf[nt]);
        }

        if (pre) {
            const int nxt = cur ^ 1;
            const int blk = kofs >> 7;
#pragma unroll
            for (int i = 0; i < 2; ++i) {
                const int idx = t + i * 256;
                const int k4 = idx >> 7, m = idx & 127;
                const float f = Fs[m][blk];
                pa[i].x *= f; pa[i].y *= f; pa[i].z *= f; pa[i].w *= f;
                if (write_att)
                    *(float4*)&obase[(size_t)(m0 + m) * Sc + kofs + k4 * 4] = pa[i];
                As[nxt][k4 * 4 + 0][m] = f2tf(pa[i].x);
                As[nxt][k4 * 4 + 1][m] = f2tf(pa[i].y);
                As[nxt][k4 * 4 + 2][m] = f2tf(pa[i].z);
                As[nxt][k4 * 4 + 3][m] = f2tf(pa[i].w);
            }
            const int vk = t >> 4, vn4 = (t & 15) * 4;
            Vs[nxt][vk][vn4 + 0] = f2tf(pv.x);
            Vs[nxt][vk][vn4 + 1] = f2tf(pv.y);
            Vs[nxt][vk][vn4 + 2] = f2tf(pv.z);
            Vs[nxt][vk][vn4 + 3] = f2tf(pv.w);
        }
        __syncthreads();
    }

    // Epilogue: ctx[b, m, h, :]
#pragma unroll
    for (int mt = 0; mt < 2; ++mt) {
        const int row0 = m0 + wm + mt * 16 + q;
#pragma unroll
        for (int nt = 0; nt < 4; ++nt) {
            const int col = wn + nt * 8 + 2 * r;
            float2 v0 = make_float2(acc[mt][nt][0], acc[mt][nt][1]);
            float2 v1 = make_float2(acc[mt][nt][2], acc[mt][nt][3]);
            *(float2*)&ctx[(size_t)(b * Sc + row0) * Dc + h * HDc + col] = v0;
            *(float2*)&ctx[(size_t)(b * Sc + row0 + 8) * Dc + h * HDc + col] = v1;
        }
    }
}

// ---------------------------------------------------------------------------
// Launch
// ---------------------------------------------------------------------------
extern "C" void kernel_launch(void* const* d_in, const int* in_sizes, int n_in,
                              void* d_out, int out_size)
{
    const float* x    = (const float*)d_in[0];
    const float* mask = (const float*)d_in[1];
    const float* Wqkv = (const float*)d_in[2];
    const float* bqkv = (const float*)d_in[3];
    const float* Wo   = (const float*)d_in[4];
    const float* bo   = (const float*)d_in[5];

    float *qkvp, *ctxp, *srawp;
    float2* statsp;
    cudaGetSymbolAddress((void**)&qkvp,  g_qkv);
    cudaGetSymbolAddress((void**)&ctxp,  g_ctx);
    cudaGetSymbolAddress((void**)&srawp, g_att);
    cudaGetSymbolAddress((void**)&statsp, g_stats);

    float* outp = (float*)d_out;
    float* attp;
    int write_att = 1;
    if ((long)out_size >= OUT_ELEMS + ATT_ELEMS) {
        attp = (float*)d_out + OUT_ELEMS;          // tuple flattened: out, then att
    } else if ((long)out_size == ATT_ELEMS) {
        attp = (float*)d_out;                      // att-only output
        outp = qkvp;                               // sink (qkv dead by then)
    } else {
        attp = srawp;                              // out-only: skip att writes
        write_att = 0;
    }

    // 1. qkv = x @ Wqkv + bqkv        [4096,3072]
    {
        dim3 grid(NQKV / 128, Mrows / 128);
        sgemm_tf32_bias<<<grid, 256>>>(x, Wqkv, bqkv, qkvp, Mrows, NQKV, Dc);
    }
    // 2. p = exp(scores - blockmax) + per-block stats
    {
        dim3 grid(Sc / 128, Sc / 128, Bc * Hc);
        scores_tf32<<<grid, 256>>>(qkvp, mask, srawp, statsp);
    }
    // 3. normalize (FMUL only) + att write + ctx = att @ V
    {
        dim3 grid(1, Sc / 128, Bc * Hc);
        ctx_tf32<<<grid, 256>>>(srawp, statsp, qkvp, attp, ctxp, write_att);
    }
    // 4. out = ctx @ Wo + bo
    {
        dim3 grid(Dc / 128, Mrows / 128);
        sgemm_tf32_bias<<<grid, 256>>>(ctxp, Wo, bo, outp, Mrows, Dc, Dc);
    }
}